// round 2
// baseline (speedup 1.0000x reference)
#include <cuda_runtime.h>

// FeedForwardQuantum: out = relu(cos(x+theta) @ W1 + b1) @ W2 + b2
// B*S = 524288 tokens, E = 8, F = 32. FMA-pipe bound -> use packed f32x2 FMA
// (2 tokens per lane) and a pure-FMA polynomial cosine (MUFU.COS throughput on
// sm_103a is 0.5 op/cyc/SM and would dominate the runtime).

using ull = unsigned long long;

static constexpr int E = 8;
static constexpr int F = 32;

// ---- packed f32x2 helpers ------------------------------------------------
__device__ __forceinline__ ull pk2(float lo, float hi) {
    ull r; asm("mov.b64 %0, {%1,%2};" : "=l"(r) : "f"(lo), "f"(hi)); return r;
}
__device__ __forceinline__ void up2(ull v, float& lo, float& hi) {
    asm("mov.b64 {%0,%1}, %2;" : "=f"(lo), "=f"(hi) : "l"(v));
}
__device__ __forceinline__ ull dup2(float f) {
    ull r; asm("mov.b64 %0, {%1,%1};" : "=l"(r) : "f"(f)); return r;
}
__device__ __forceinline__ ull fma2(ull a, ull b, ull c) {
    ull r; asm("fma.rn.f32x2 %0, %1, %2, %3;" : "=l"(r) : "l"(a), "l"(b), "l"(c)); return r;
}
__device__ __forceinline__ ull add2(ull a, ull b) {
    ull r; asm("add.rn.f32x2 %0, %1, %2;" : "=l"(r) : "l"(a), "l"(b)); return r;
}
__device__ __forceinline__ ull mul2(ull a, ull b) {
    ull r; asm("mul.rn.f32x2 %0, %1, %2;" : "=l"(r) : "l"(a), "l"(b)); return r;
}

// ---- packed cosine: 2pi Cody-Waite reduction + even Taylor deg-14 --------
// |arg| here is ~N(0, sqrt(2)) so |a| < ~10; reduction valid far beyond that.
// Max abs error ~1e-6 on [-pi, pi] — way under the 1e-3 rel_err budget.
struct CosC {
    ull inv2pi, mag, nmag, nhi, plo;
    ull c7, c6, c5, c4, c3, c2, c1, c0;
};
__device__ __forceinline__ CosC make_cosc() {
    CosC c;
    c.inv2pi = dup2(0.15915494309189535f);
    c.mag    = dup2(12582912.0f);              // 1.5 * 2^23 round-to-nearest magic
    c.nmag   = dup2(-12582912.0f);
    c.nhi    = dup2(-6.28318548202514648f);    // -float(2*pi)
    c.plo    = dup2(1.74845553e-7f);           // -(2*pi - float(2*pi))
    c.c7 = dup2(-1.14707456e-11f);
    c.c6 = dup2(2.08767570e-9f);
    c.c5 = dup2(-2.75573192e-7f);
    c.c4 = dup2(2.48015873e-5f);
    c.c3 = dup2(-1.38888889e-3f);
    c.c2 = dup2(4.16666667e-2f);
    c.c1 = dup2(-0.5f);
    c.c0 = dup2(1.0f);
    return c;
}
__device__ __forceinline__ ull pcos2(ull a, const CosC& c) {
    ull km = fma2(a, c.inv2pi, c.mag);   // round(a / 2pi) via magic
    ull k  = add2(km, c.nmag);
    ull r  = fma2(k, c.nhi, a);          // Cody-Waite step 1
    r      = fma2(k, c.plo, r);          // Cody-Waite step 2; r in [-pi, pi]
    ull t  = mul2(r, r);
    ull p  = fma2(c.c7, t, c.c6);
    p = fma2(p, t, c.c5);
    p = fma2(p, t, c.c4);
    p = fma2(p, t, c.c3);
    p = fma2(p, t, c.c2);
    p = fma2(p, t, c.c1);
    p = fma2(p, t, c.c0);
    return p;
}

// ---- kernel --------------------------------------------------------------
// 128 threads/block, 4 tokens/thread (2 packed pairs) -> 512 tokens/block.
// Warp owns a contiguous 128-token tile; thread t takes tokens t, t+32,
// t+64, t+96 (pairs (t,t+32) and (t+64,t+96)).
__global__ __launch_bounds__(128, 4)
void ffq_kernel(const float* __restrict__ x,
                const float* __restrict__ theta,
                const float* __restrict__ w1,
                const float* __restrict__ b1,
                const float* __restrict__ w2,
                const float* __restrict__ b2,
                float* __restrict__ out,
                int ntok) {
    // Weights duplicated into both f32x2 halves so packed-FMA operands come
    // straight out of LDS with no per-use dup MOVs. w1 stored transposed [F][E].
    __shared__ __align__(16) ull s_w1d[F * E];
    __shared__ __align__(16) ull s_w2d[F * E];
    __shared__ __align__(16) ull s_b1d[F];
    __shared__ __align__(16) ull s_b2d[E];
    __shared__ __align__(16) ull s_thd[E];

    const int tid = threadIdx.x;
    for (int i = tid; i < F * E; i += 128) {
        int e = i & 7, f = i >> 3;
        s_w1d[i] = dup2(w1[e * F + f]);   // transpose: [F][E]
        s_w2d[i] = dup2(w2[i]);           // already [F][E]
    }
    if (tid < F) s_b1d[tid] = dup2(b1[tid]);
    if (tid < E) { s_b2d[tid] = dup2(b2[tid]); s_thd[tid] = dup2(theta[tid]); }
    __syncthreads();

    const int lane = tid & 31;
    const int warp = tid >> 5;
    const int base = blockIdx.x * 512 + warp * 128 + lane;
    int t[4];
    t[0] = base; t[1] = base + 32; t[2] = base + 64; t[3] = base + 96;

    const float4* x4 = reinterpret_cast<const float4*>(x);
    float xv[4][8];
#pragma unroll
    for (int j = 0; j < 4; ++j) {
        int ti = min(t[j], ntok - 1);     // clamp (tail-safe); stores are guarded
        float4 a = x4[ti * 2];
        float4 b = x4[ti * 2 + 1];
        xv[j][0] = a.x; xv[j][1] = a.y; xv[j][2] = a.z; xv[j][3] = a.w;
        xv[j][4] = b.x; xv[j][5] = b.y; xv[j][6] = b.z; xv[j][7] = b.w;
    }

    ull q2[2][E];
    {
        const CosC cc = make_cosc();
#pragma unroll
        for (int p = 0; p < 2; ++p) {
#pragma unroll
            for (int e = 0; e < E; ++e) {
                ull a = add2(pk2(xv[2 * p][e], xv[2 * p + 1][e]), s_thd[e]);
                q2[p][e] = pcos2(a, cc);
            }
        }
    }

    ull o2[2][E];
#pragma unroll
    for (int p = 0; p < 2; ++p)
#pragma unroll
        for (int e = 0; e < E; ++e) o2[p][e] = s_b2d[e];

#pragma unroll 4
    for (int f = 0; f < F; ++f) {
        const ulonglong2* w1r = reinterpret_cast<const ulonglong2*>(&s_w1d[f * E]);
        const ulonglong2* w2r = reinterpret_cast<const ulonglong2*>(&s_w2d[f * E]);
        ulonglong2 w1v0 = w1r[0], w1v1 = w1r[1], w1v2 = w1r[2], w1v3 = w1r[3];
        ulonglong2 w2v0 = w2r[0], w2v1 = w2r[1], w2v2 = w2r[2], w2v3 = w2r[3];
        ull b1v = s_b1d[f];
#pragma unroll
        for (int p = 0; p < 2; ++p) {
            ull h = b1v;
            h = fma2(q2[p][0], w1v0.x, h);
            h = fma2(q2[p][1], w1v0.y, h);
            h = fma2(q2[p][2], w1v1.x, h);
            h = fma2(q2[p][3], w1v1.y, h);
            h = fma2(q2[p][4], w1v2.x, h);
            h = fma2(q2[p][5], w1v2.y, h);
            h = fma2(q2[p][6], w1v3.x, h);
            h = fma2(q2[p][7], w1v3.y, h);
            // ReLU per half on the ALU pipe (FMNMX) — doesn't contend with FMA.
            float hl, hh;
            up2(h, hl, hh);
            hl = fmaxf(hl, 0.0f);
            hh = fmaxf(hh, 0.0f);
            h = pk2(hl, hh);
            o2[p][0] = fma2(h, w2v0.x, o2[p][0]);
            o2[p][1] = fma2(h, w2v0.y, o2[p][1]);
            o2[p][2] = fma2(h, w2v1.x, o2[p][2]);
            o2[p][3] = fma2(h, w2v1.y, o2[p][3]);
            o2[p][4] = fma2(h, w2v2.x, o2[p][4]);
            o2[p][5] = fma2(h, w2v2.y, o2[p][5]);
            o2[p][6] = fma2(h, w2v3.x, o2[p][6]);
            o2[p][7] = fma2(h, w2v3.y, o2[p][7]);
        }
    }

    float4* o4 = reinterpret_cast<float4*>(out);
#pragma unroll
    for (int p = 0; p < 2; ++p) {
        float lo[8], hi[8];
#pragma unroll
        for (int e = 0; e < E; ++e) up2(o2[p][e], lo[e], hi[e]);
        int ta = t[2 * p], tb = t[2 * p + 1];
        if (ta < ntok) {
            o4[ta * 2]     = make_float4(lo[0], lo[1], lo[2], lo[3]);
            o4[ta * 2 + 1] = make_float4(lo[4], lo[5], lo[6], lo[7]);
        }
        if (tb < ntok) {
            o4[tb * 2]     = make_float4(hi[0], hi[1], hi[2], hi[3]);
            o4[tb * 2 + 1] = make_float4(hi[4], hi[5], hi[6], hi[7]);
        }
    }
}

extern "C" void kernel_launch(void* const* d_in, const int* in_sizes, int n_in,
                              void* d_out, int out_size) {
    const float* x     = (const float*)d_in[0];
    const float* theta = (const float*)d_in[1];
    const float* w1    = (const float*)d_in[2];
    const float* b1    = (const float*)d_in[3];
    const float* w2    = (const float*)d_in[4];
    const float* b2    = (const float*)d_in[5];
    float* out = (float*)d_out;

    // ntok = B*S. Derive from out_size (== ntok * E) as the authority; it is
    // independent of input ordering. Falls back to in_sizes[0]/E identical value.
    int ntok = out_size / E;
    if (ntok <= 0) ntok = in_sizes[0] / E;
    int grid = (ntok + 511) / 512;              // 512 tokens per block
    ffq_kernel<<<grid, 128>>>(x, theta, w1, b1, w2, b2, out, ntok);
}